// round 16
// baseline (speedup 1.0000x reference)
#include <cuda_runtime.h>
#include <cuda_fp16.h>
#include <cstdint>
#include <math.h>

// ---------------------------------------------------------------- constants
#define BB 8
#define SS 2048
#define NNB 16
#define HH 256
#define MM (BB * SS)          // 16384 tokens
#define G4 (4 * HH)           // 1024
#define K2 768                // fused K for gates GEMM

// -------- scratch: device globals, referenced ONLY from device code --------
__device__ float g_gbias[BB * G4];                  // permuted layout
__device__ __half g_A2[(size_t)MM * K2];            // [h | x | hn] fp16  24 MB
__device__ __half g_B2[G4 * K2];                    // perm([Wh;U;Wn]^T)  1.5 MB
__device__ __half g_B1[HH * HH];                    // Wn_a^T (n-major)
__device__ __half g_AG[(size_t)MM * HH];            // neighbor agg       8 MB

// ---------------------------------------------------------------- PTX utils
__device__ __forceinline__ uint32_t smem_u32(const void* p) {
    uint32_t a;
    asm("{ .reg .u64 t; cvta.to.shared.u64 t, %1; cvt.u32.u64 %0, t; }"
        : "=r"(a) : "l"(p));
    return a;
}
__device__ __forceinline__ void cp_async16(uint32_t dst, const void* src) {
    asm volatile("cp.async.cg.shared.global [%0], [%1], 16;"
                 :: "r"(dst), "l"(src) : "memory");
}
__device__ __forceinline__ void cp_commit() {
    asm volatile("cp.async.commit_group;" ::: "memory");
}
template <int N>
__device__ __forceinline__ void cp_wait() {
    asm volatile("cp.async.wait_group %0;" :: "n"(N) : "memory");
}
#define LDSM_X4(r0, r1, r2, r3, addr)                                            \
    asm volatile("ldmatrix.sync.aligned.m8n8.x4.shared.b16 {%0,%1,%2,%3}, [%4];" \
                 : "=r"(r0), "=r"(r1), "=r"(r2), "=r"(r3) : "r"(addr))
#define MMA_F16(d0, d1, d2, d3, a0, a1, a2, a3, b0, b1)                          \
    asm volatile("mma.sync.aligned.m16n8k16.row.col.f32.f16.f16.f32 "            \
                 "{%0,%1,%2,%3}, {%4,%5,%6,%7}, {%8,%9}, {%0,%1,%2,%3};"         \
                 : "+f"(d0), "+f"(d1), "+f"(d2), "+f"(d3)                        \
                 : "r"(a0), "r"(a1), "r"(a2), "r"(a3), "r"(b0), "r"(b1))
#define MMA4(Cn, a0, a1, a2, a3, b0, b1)                                         \
    MMA_F16(Cn##_0, Cn##_1, Cn##_2, Cn##_3, a0, a1, a2, a3, b0, b1)

__device__ __forceinline__ float sigmoidf_(float x) {
    return 1.0f / (1.0f + expf(-x));
}

// N permutation for the gates GEMM (thread-local i/f/o/u grouping):
// n = q*256 + idx; blk = idx>>5; lh = idx&31
// n' = blk*128 + (lh>>4)*64 + (q + 4*((lh>>3)&1))*8 + (lh&7)
__device__ __forceinline__ int perm_n(int n) {
    int q = n >> 8, idx = n & 255;
    int lh = idx & 31;
    return (idx >> 5) * 128 + (lh >> 4) * 64 + ((q + 4 * ((lh >> 3) & 1)) << 3) +
           (lh & 7);
}

// ---------------------------------------------------------------- prep_W
// Fused: conv_B (weights -> fp16, transposed/permuted) + gbias.
// Blocks [0, NB_CONVB): conv_B ranges; blocks [NB_CONVB, NB_CONVB+32): gbias.
#define NB_CONVB ((G4 * K2 + HH * HH + 255) / 256)
__global__ void prep_W(const float* __restrict__ Wh, const float* __restrict__ U,
                       const float* __restrict__ Wn, const float* __restrict__ Wn_a,
                       const float* __restrict__ g, const float* __restrict__ V,
                       const float* __restrict__ Vb) {
    if (blockIdx.x < NB_CONVB) {
        int t = blockIdx.x * 256 + threadIdx.x;
        if (t < G4 * K2) {
            int k = t >> 10, n = t & 1023;
            float v = (k < 256) ? Wh[(size_t)k * G4 + n]
                    : (k < 512) ? U[(size_t)(k - 256) * G4 + n]
                                : Wn[(size_t)(k - 512) * G4 + n];
            g_B2[(size_t)perm_n(n) * K2 + k] = __float2half_rn(v);
        } else {
            int t2 = t - G4 * K2;
            if (t2 < HH * HH) {
                int k = t2 >> 8, n = t2 & 255;
                g_B1[n * HH + k] = __float2half_rn(Wn_a[k * HH + n]);
            }
        }
    } else {
        __shared__ float gs[HH];
        int bid = blockIdx.x - NB_CONVB;          // 0..31
        int b = bid & 7, seg = bid >> 3;          // batch, quarter of G4
        int t = threadIdx.x;
        gs[t] = g[b * HH + t];
        __syncthreads();
        int n = seg * 256 + t;
        float acc = Vb[n];
        #pragma unroll 4
        for (int k = 0; k < HH; ++k) acc += gs[k] * V[k * G4 + n];
        g_gbias[b * G4 + perm_n(n)] = acc;
    }
}

// ---------------------------------------------------------------- prep_A
// Fused: conv_A ([h|x] -> A2 cols 0..511 fp16) + gather (masked neighbor sum).
// Blocks [0, 8192): conv_A; blocks [8192, 12288): gather.
__global__ void prep_A(const float* __restrict__ h, const float* __restrict__ x,
                       const int* __restrict__ idx, const int* __restrict__ mask) {
    if (blockIdx.x < 8192) {
        int t = blockIdx.x * 256 + threadIdx.x;   // MM*128 lanes
        int m = t >> 7;
        int c = (t & 127) * 4;                    // 0..508
        const float* src = (c < 256) ? (h + (size_t)m * HH + c)
                                     : (x + (size_t)m * HH + (c - 256));
        float4 v = *(const float4*)src;
        size_t o = (size_t)m * K2 + c;
        *(__half2*)(g_A2 + o)     = __floats2half2_rn(v.x, v.y);
        *(__half2*)(g_A2 + o + 2) = __floats2half2_rn(v.z, v.w);
    } else {
        int tid = (blockIdx.x - 8192) * 256 + threadIdx.x;
        int token = tid >> 6;
        int lane = tid & 63;
        int b = token >> 11;
        const int* ip = idx + token * NNB;
        const int* mp = mask + token * NNB;
        const float* hb = h + (size_t)b * SS * HH;
        float4 acc = make_float4(0.f, 0.f, 0.f, 0.f);
        #pragma unroll
        for (int n = 0; n < NNB; ++n) {
            int id = ip[n];
            int mk = mp[n];
            if (mk != 0 && id > 0) {
                const float4 v =
                    *(const float4*)(hb + (size_t)(id - 1) * HH + lane * 4);
                acc.x += v.x; acc.y += v.y; acc.z += v.z; acc.w += v.w;
            }
        }
        size_t o = (size_t)token * HH + lane * 4;
        *(__half2*)(g_AG + o)     = __floats2half2_rn(acc.x, acc.y);
        *(__half2*)(g_AG + o + 2) = __floats2half2_rn(acc.z, acc.w);
    }
}

// ---------------------------------------------------------------- mma GEMM
// 128x128 block, 8 warps (32m x 64n per warp), fp16 single-pass, fp32 accum.
// DOUBLE-CHUNK stages: each pipeline stage = 2 K-chunks (BK=32 total),
// 3-deep cp.async pipeline, ONE __syncthreads per 2 chunks, 48 KB static smem.
// Per chunk sub-tile: A(+0) B(+4K), 128 rows x 32 B,
// swizzle: off = row*32 + (kb ^ ((row&4)<<2)).
#define CHUNK_B 8192               // one chunk: A 4K + B 4K
#define STG2_B 16384               // double-chunk stage

#define DECL4(p) float p##_0 = 0.f, p##_1 = 0.f, p##_2 = 0.f, p##_3 = 0.f

#define BJ_BLOCK(SB, bj, CA0, CA1, CB0, CB1)                                   \
    do {                                                                       \
        int rowb = wn * 64 + (bj) * 16 + (lid & 15);                           \
        uint32_t offb = (SB) + 4096 + rowb * 32 + (KB ^ ((rowb & 4) << 2));    \
        uint32_t bh0, bh1, bh2, bh3;                                           \
        LDSM_X4(bh0, bh1, bh2, bh3, offb);                                     \
        MMA4(CA0, ah0_0, ah0_1, ah0_2, ah0_3, bh0, bh2);                       \
        MMA4(CA1, ah0_0, ah0_1, ah0_2, ah0_3, bh1, bh3);                       \
        MMA4(CB0, ah1_0, ah1_1, ah1_2, ah1_3, bh0, bh2);                       \
        MMA4(CB1, ah1_0, ah1_1, ah1_2, ah1_3, bh1, bh3);                       \
    } while (0)

#define COMPUTE_CHUNK(SBexpr)                                                  \
    do {                                                                       \
        const uint32_t SB = (SBexpr);                                          \
        uint32_t ah0_0, ah0_1, ah0_2, ah0_3, ah1_0, ah1_1, ah1_2, ah1_3;       \
        {                                                                      \
            int rowa = wm * 32 + (lid & 15);                                   \
            uint32_t offa = SB + rowa * 32 + (KB ^ ((rowa & 4) << 2));         \
            LDSM_X4(ah0_0, ah0_1, ah0_2, ah0_3, offa);                         \
            int rowc = rowa + 16;                                              \
            uint32_t offc = SB + rowc * 32 + (KB ^ ((rowc & 4) << 2));         \
            LDSM_X4(ah1_0, ah1_1, ah1_2, ah1_3, offc);                         \
        }                                                                      \
        BJ_BLOCK(SB, 0, C00, C01, C10, C11);                                   \
        BJ_BLOCK(SB, 1, C02, C03, C12, C13);                                   \
        BJ_BLOCK(SB, 2, C04, C05, C14, C15);                                   \
        BJ_BLOCK(SB, 3, C06, C07, C16, C17);                                   \
    } while (0)

#define HN_ST(Cn, MI, NI)                                                      \
    do {                                                                       \
        int col = bn + wn * 64 + (NI) * 8 + tq * 2;                            \
        int m0 = bm + wm * 32 + (MI) * 16 + quad;                              \
        size_t o = (size_t)m0 * K2 + 512 + col;                                \
        *(__half2*)(g_A2 + o) =                                                \
            __floats2half2_rn(Cn##_0 * 0.0625f, Cn##_1 * 0.0625f);             \
        o = (size_t)(m0 + 8) * K2 + 512 + col;                                 \
        *(__half2*)(g_A2 + o) =                                                \
            __floats2half2_rn(Cn##_2 * 0.0625f, Cn##_3 * 0.0625f);             \
    } while (0)

#define LSTM_E(i0, i1, f0, f1, o0, o1, u0, u1, MME, HCE, gI, gF, gO, gU)       \
    do {                                                                       \
        float2 cv = *(const float2*)(cin + (size_t)(MME) * HH + (HCE));        \
        float ivx = (i0) + gI.x, ivy = (i1) + gI.y;                            \
        float fvx = (f0) + gF.x, fvy = (f1) + gF.y;                            \
        float ovx = (o0) + gO.x, ovy = (o1) + gO.y;                            \
        float uvx = (u0) + gU.x, uvy = (u1) + gU.y;                            \
        float ncx = sigmoidf_(fvx) * cv.x + sigmoidf_(ivx) * tanhf(uvx);       \
        float ncy = sigmoidf_(fvy) * cv.y + sigmoidf_(ivy) * tanhf(uvy);       \
        float2 nh = make_float2(sigmoidf_(ovx) * tanhf(ncx),                   \
                                sigmoidf_(ovy) * tanhf(ncy));                  \
        *(float2*)(out + (size_t)(MME) * HH + (HCE)) = nh;                     \
        *(float2*)(out + (size_t)MM * HH + (size_t)(MME) * HH + (HCE)) =       \
            make_float2(ncx, ncy);                                             \
    } while (0)

// MODE0: hn = agg @ Wn_a^T / 16 -> A2 cols 512..767 (fp16), KTOT=256
// MODE1: gates(perm cols) + gbias -> fused LSTM -> out, KTOT=768
template <int MODE>
__global__ __launch_bounds__(256, 2)
void mma_gemm(const float* __restrict__ cin, float* __restrict__ out) {
    constexpr int KTOT = (MODE == 0) ? HH : K2;
    constexpr int NS = KTOT / 32;                // double-chunk stages

    const __half* __restrict__ A = (MODE == 0) ? g_AG : g_A2;
    const __half* __restrict__ B = (MODE == 0) ? g_B1 : g_B2;

    __shared__ __align__(128) char smem_buf[3 * STG2_B];   // 48 KB static
    const uint32_t sb = smem_u32(smem_buf);
    const int tid = threadIdx.x;
    const int wid = tid >> 5, lid = tid & 31;
    const int wm = wid & 3, wn = wid >> 2;       // 4 x 2 warp grid
    const int bm = blockIdx.y * 128, bn = blockIdx.x * 128;

    DECL4(C00); DECL4(C01); DECL4(C02); DECL4(C03);
    DECL4(C04); DECL4(C05); DECL4(C06); DECL4(C07);
    DECL4(C10); DECL4(C11); DECL4(C12); DECL4(C13);
    DECL4(C14); DECL4(C15); DECL4(C16); DECL4(C17);

    // stage loader: one 16B cp.async per tile per chunk (2 chunks per stage)
    const int lrow = tid >> 1;                   // 0..127
    const uint32_t loff = (uint32_t)lrow * 32 +
                          (((uint32_t)(tid & 1) * 16) ^ ((lrow & 4) << 2));
    const int le8 = (tid & 1) * 8;               // 8 halves = 16 B

#define LOAD_STAGE2(st, s2)                                                    \
    {                                                                          \
        const int kA_ = (s2) * 32;                                             \
        const uint32_t b0_ = sb + (uint32_t)(st) * STG2_B + loff;              \
        const size_t gaA_ = (size_t)(bm + lrow) * KTOT + kA_ + le8;            \
        const size_t gbA_ = (size_t)(bn + lrow) * KTOT + kA_ + le8;            \
        cp_async16(b0_, A + gaA_);                                             \
        cp_async16(b0_ + 4096, B + gbA_);                                      \
        cp_async16(b0_ + CHUNK_B, A + gaA_ + 16);                              \
        cp_async16(b0_ + CHUNK_B + 4096, B + gbA_ + 16);                       \
    }

    // 3-stage prologue: double-stages 0 and 1 in flight
    LOAD_STAGE2(0, 0);
    cp_commit();
    LOAD_STAGE2(1, 1);
    cp_commit();

    int s_cur = 0;
    int s_nxt = 2;

    #pragma unroll 1
    for (int s2 = 0; s2 < NS; ++s2) {
        cp_wait<1>();          // double-stage s2 landed
        __syncthreads();       // all warps done reading buffer s_nxt
        if (s2 + 2 < NS) LOAD_STAGE2(s_nxt, s2 + 2);
        cp_commit();           // uniform group accounting (empty ok)

        const uint32_t KB = (uint32_t)(lid >> 4) * 16;
        const uint32_t SBase = sb + (uint32_t)s_cur * STG2_B;
        COMPUTE_CHUNK(SBase);
        COMPUTE_CHUNK(SBase + CHUNK_B);

        s_cur = (s_cur == 2) ? 0 : s_cur + 1;
        s_nxt = (s_nxt == 2) ? 0 : s_nxt + 1;
    }
#undef LOAD_STAGE2

    __syncthreads();

    // -------- epilogue --------
    const int quad = lid >> 2, tq = lid & 3;

    if (MODE == 0) {
        HN_ST(C00, 0, 0); HN_ST(C01, 0, 1); HN_ST(C02, 0, 2); HN_ST(C03, 0, 3);
        HN_ST(C04, 0, 4); HN_ST(C05, 0, 5); HN_ST(C06, 0, 6); HN_ST(C07, 0, 7);
        HN_ST(C10, 1, 0); HN_ST(C11, 1, 1); HN_ST(C12, 1, 2); HN_ST(C13, 1, 3);
        HN_ST(C14, 1, 4); HN_ST(C15, 1, 5); HN_ST(C16, 1, 6); HN_ST(C17, 1, 7);
    } else {
        const int bi = blockIdx.y >> 4;          // batch (16 m-tiles per batch)
        const float* gbp = g_gbias + bi * G4 + blockIdx.x * 128 + wn * 64 + tq * 2;
        float2 gI0 = *(const float2*)(gbp + 0);
        float2 gF0 = *(const float2*)(gbp + 8);
        float2 gO0 = *(const float2*)(gbp + 16);
        float2 gU0 = *(const float2*)(gbp + 24);
        float2 gI1 = *(const float2*)(gbp + 32);
        float2 gF1 = *(const float2*)(gbp + 40);
        float2 gO1 = *(const float2*)(gbp + 48);
        float2 gU1 = *(const float2*)(gbp + 56);
        const int m0 = bm + wm * 32 + quad;
        const int hc0 = blockIdx.x * 32 + wn * 16 + tq * 2;
        const int hc1 = hc0 + 8;
        // mi=0
        LSTM_E(C00_0, C00_1, C01_0, C01_1, C02_0, C02_1, C03_0, C03_1,
               m0, hc0, gI0, gF0, gO0, gU0);
        LSTM_E(C00_2, C00_3, C01_2, C01_3, C02_2, C02_3, C03_2, C03_3,
               m0 + 8, hc0, gI0, gF0, gO0, gU0);
        LSTM_E(C04_0, C04_1, C05_0, C05_1, C06_0, C06_1, C07_0, C07_1,
               m0, hc1, gI1, gF1, gO1, gU1);
        LSTM_E(C04_2, C04_3, C05_2, C05_3, C06_2, C06_3, C07_2, C07_3,
               m0 + 8, hc1, gI1, gF1, gO1, gU1);
        // mi=1
        LSTM_E(C10_0, C10_1, C11_0, C11_1, C12_0, C12_1, C13_0, C13_1,
               m0 + 16, hc0, gI0, gF0, gO0, gU0);
        LSTM_E(C10_2, C10_3, C11_2, C11_3, C12_2, C12_3, C13_2, C13_3,
               m0 + 24, hc0, gI0, gF0, gO0, gU0);
        LSTM_E(C14_0, C14_1, C15_0, C15_1, C16_0, C16_1, C17_0, C17_1,
               m0 + 16, hc1, gI1, gF1, gO1, gU1);
        LSTM_E(C14_2, C14_3, C15_2, C15_3, C16_2, C16_3, C17_2, C17_3,
               m0 + 24, hc1, gI1, gF1, gO1, gU1);
    }
}

// ----------------------------------------------------------------------------
extern "C" void kernel_launch(void* const* d_in, const int* in_sizes, int n_in,
                              void* d_out, int out_size) {
    const float* x    = (const float*)d_in[0];
    const float* h    = (const float*)d_in[1];
    const float* c    = (const float*)d_in[2];
    const float* g    = (const float*)d_in[3];
    const int*   idx  = (const int*)d_in[4];
    const int*   mask = (const int*)d_in[5];
    // d_in[6] Wh_a, d_in[8..12]: unused — softmax over logits*1e-25 is exactly
    // uniform in fp32, so the attention score is 1/16 for every neighbor.
    const float* Wn_a = (const float*)d_in[7];
    const float* Wh   = (const float*)d_in[13];
    const float* Wn   = (const float*)d_in[14];
    const float* U    = (const float*)d_in[15];
    const float* V    = (const float*)d_in[16];
    const float* Vb   = (const float*)d_in[17];
    float* out = (float*)d_out;

    // 1. weights + bias prep (fused conv_B + gbias)
    prep_W<<<NB_CONVB + 32, 256>>>(Wh, U, Wn, Wn_a, g, V, Vb);
    // 2. activations prep (fused conv_A + gather)
    prep_A<<<8192 + 4096, 256>>>(h, x, idx, mask);
    // 3. hn = agg @ Wn_a^T-layout / 16   (M=16384, N=256, K=256)
    mma_gemm<0><<<dim3(2, MM / 128), 256>>>(nullptr, nullptr);
    // 4. gates(+fused LSTM) -> out      (M=16384, N=1024 permuted, K=768)
    mma_gemm<1><<<dim3(8, MM / 128), 256>>>(c, out);
}

// round 17
// speedup vs baseline: 1.2059x; 1.2059x over previous
#include <cuda_runtime.h>
#include <cuda_fp16.h>
#include <cstdint>
#include <math.h>

// ---------------------------------------------------------------- constants
#define BB 8
#define SS 2048
#define NNB 16
#define HH 256
#define MM (BB * SS)          // 16384 tokens
#define G4 (4 * HH)           // 1024
#define K2 768                // fused K for gates GEMM

// -------- scratch: device globals, referenced ONLY from device code --------
__device__ float g_gbias[BB * G4];                  // permuted layout
__device__ __half g_A2[(size_t)MM * K2];            // [h | x | agg] fp16  24 MB
__device__ __half g_B2[G4 * K2];                    // perm([Wh;U;W']^T)   1.5 MB

// ---------------------------------------------------------------- PTX utils
__device__ __forceinline__ uint32_t smem_u32(const void* p) {
    uint32_t a;
    asm("{ .reg .u64 t; cvta.to.shared.u64 t, %1; cvt.u32.u64 %0, t; }"
        : "=r"(a) : "l"(p));
    return a;
}
__device__ __forceinline__ void cp_async16(uint32_t dst, const void* src) {
    asm volatile("cp.async.cg.shared.global [%0], [%1], 16;"
                 :: "r"(dst), "l"(src) : "memory");
}
__device__ __forceinline__ void cp_commit() {
    asm volatile("cp.async.commit_group;" ::: "memory");
}
template <int N>
__device__ __forceinline__ void cp_wait() {
    asm volatile("cp.async.wait_group %0;" :: "n"(N) : "memory");
}
#define LDSM_X4(r0, r1, r2, r3, addr)                                            \
    asm volatile("ldmatrix.sync.aligned.m8n8.x4.shared.b16 {%0,%1,%2,%3}, [%4];" \
                 : "=r"(r0), "=r"(r1), "=r"(r2), "=r"(r3) : "r"(addr))
#define MMA_F16(d0, d1, d2, d3, a0, a1, a2, a3, b0, b1)                          \
    asm volatile("mma.sync.aligned.m16n8k16.row.col.f32.f16.f16.f32 "            \
                 "{%0,%1,%2,%3}, {%4,%5,%6,%7}, {%8,%9}, {%0,%1,%2,%3};"         \
                 : "+f"(d0), "+f"(d1), "+f"(d2), "+f"(d3)                        \
                 : "r"(a0), "r"(a1), "r"(a2), "r"(a3), "r"(b0), "r"(b1))
#define MMA4(Cn, a0, a1, a2, a3, b0, b1)                                         \
    MMA_F16(Cn##_0, Cn##_1, Cn##_2, Cn##_3, a0, a1, a2, a3, b0, b1)

__device__ __forceinline__ float sigmoidf_(float x) {
    return 1.0f / (1.0f + expf(-x));
}

// N permutation for the gates GEMM (thread-local i/f/o/u grouping):
// n = q*256 + idx; blk = idx>>5; lh = idx&31
// n' = blk*128 + (lh>>4)*64 + (q + 4*((lh>>3)&1))*8 + (lh&7)
__device__ __forceinline__ int perm_n(int n) {
    int q = n >> 8, idx = n & 255;
    int lh = idx & 31;
    return (idx >> 5) * 128 + (lh >> 4) * 64 + ((q + 4 * ((lh >> 3) & 1)) << 3) +
           (lh & 7);
}

// ---------------------------------------------------------------- prep_all
// One launch, independent block ranges:
//  [0, 64):            W' = (Wn_a @ Wn)/16 -> g_B2 cols 512..767 (fp32 GEMM)
//  [64, 96):           gbias = g@V + Vb (permuted)
//  [96, 3168):         conv_B2: [Wh;U] -> g_B2 cols 0..511 (fp16, n-major, perm)
//  [3168, 11360):      conv_A:  [h|x]  -> g_A2 cols 0..511 (fp16)
//  [11360, 15456):     gather:  masked neighbor sum -> g_A2 cols 512..767
#define NB_WP 64
#define NB_GB 32
#define NB_CB 3072        // (G4 * 512) / 256 elements per thread=1
#define NB_CA 8192        // MM*128 lanes / 256
#define NB_GA 4096        // MM*64 lanes / 256
#define NB_TOT (NB_WP + NB_GB + NB_CB + NB_CA + NB_GA)

__global__ void prep_all(const float* __restrict__ h, const float* __restrict__ x,
                         const int* __restrict__ idx, const int* __restrict__ mask,
                         const float* __restrict__ Wh, const float* __restrict__ U,
                         const float* __restrict__ Wn, const float* __restrict__ Wn_a,
                         const float* __restrict__ g, const float* __restrict__ V,
                         const float* __restrict__ Vb) {
    __shared__ float As[16][64];
    __shared__ float Bsm[16][64];
    __shared__ float gs[HH];

    const int bx = blockIdx.x;
    const int t = threadIdx.x;

    if (bx < NB_WP) {
        // ---- W'[j,n] = (1/16) * sum_k Wn_a[j,k] * Wn[k,n];  64x64 tile ----
        int jt = bx >> 4, nt = bx & 15;
        int j0 = jt * 64, n0 = nt * 64;
        int ty = t >> 4, tx = t & 15;
        float acc[4][4];
        #pragma unroll
        for (int i = 0; i < 4; ++i)
            #pragma unroll
            for (int j = 0; j < 4; ++j) acc[i][j] = 0.f;
        for (int kk0 = 0; kk0 < HH; kk0 += 16) {
            #pragma unroll
            for (int i = 0; i < 4; ++i) {
                int e = t * 4 + i;          // 0..1023
                int ja = e >> 4, ka = e & 15;
                As[ka][ja] = Wn_a[(j0 + ja) * HH + kk0 + ka];
                int kb = e >> 6, nb = e & 63;
                Bsm[kb][nb] = Wn[(kk0 + kb) * G4 + n0 + nb];
            }
            __syncthreads();
            #pragma unroll
            for (int k = 0; k < 16; ++k) {
                float a0 = As[k][ty * 4 + 0], a1 = As[k][ty * 4 + 1];
                float a2 = As[k][ty * 4 + 2], a3 = As[k][ty * 4 + 3];
                float b0 = Bsm[k][tx * 4 + 0], b1 = Bsm[k][tx * 4 + 1];
                float b2 = Bsm[k][tx * 4 + 2], b3 = Bsm[k][tx * 4 + 3];
                acc[0][0] += a0 * b0; acc[0][1] += a0 * b1;
                acc[0][2] += a0 * b2; acc[0][3] += a0 * b3;
                acc[1][0] += a1 * b0; acc[1][1] += a1 * b1;
                acc[1][2] += a1 * b2; acc[1][3] += a1 * b3;
                acc[2][0] += a2 * b0; acc[2][1] += a2 * b1;
                acc[2][2] += a2 * b2; acc[2][3] += a2 * b3;
                acc[3][0] += a3 * b0; acc[3][1] += a3 * b1;
                acc[3][2] += a3 * b2; acc[3][3] += a3 * b3;
            }
            __syncthreads();
        }
        #pragma unroll
        for (int dj = 0; dj < 4; ++dj)
            #pragma unroll
            for (int dn = 0; dn < 4; ++dn) {
                int n = n0 + tx * 4 + dn;
                int j = j0 + ty * 4 + dj;
                g_B2[(size_t)perm_n(n) * K2 + 512 + j] =
                    __float2half_rn(acc[dj][dn] * 0.0625f);
            }
    } else if (bx < NB_WP + NB_GB) {
        // ---- gbias ----
        int bid = bx - NB_WP;
        int b = bid & 7, seg = bid >> 3;
        gs[t] = g[b * HH + t];
        __syncthreads();
        int n = seg * 256 + t;
        float acc = Vb[n];
        #pragma unroll 4
        for (int k = 0; k < HH; ++k) acc += gs[k] * V[k * G4 + n];
        g_gbias[b * G4 + perm_n(n)] = acc;
    } else if (bx < NB_WP + NB_GB + NB_CB) {
        // ---- conv_B2: k in [0,512) from Wh (k<256) / U (k-256) ----
        int e = (bx - NB_WP - NB_GB) * 256 + t;   // 0 .. G4*512-1
        int k = e >> 10, n = e & 1023;
        float v = (k < 256) ? Wh[(size_t)k * G4 + n]
                            : U[(size_t)(k - 256) * G4 + n];
        g_B2[(size_t)perm_n(n) * K2 + k] = __float2half_rn(v);
    } else if (bx < NB_WP + NB_GB + NB_CB + NB_CA) {
        // ---- conv_A: [h|x] -> A2 cols 0..511 ----
        int e = (bx - NB_WP - NB_GB - NB_CB) * 256 + t;  // MM*128 lanes
        int m = e >> 7;
        int c = (e & 127) * 4;
        const float* src = (c < 256) ? (h + (size_t)m * HH + c)
                                     : (x + (size_t)m * HH + (c - 256));
        float4 v = *(const float4*)src;
        size_t o = (size_t)m * K2 + c;
        *(__half2*)(g_A2 + o)     = __floats2half2_rn(v.x, v.y);
        *(__half2*)(g_A2 + o + 2) = __floats2half2_rn(v.z, v.w);
    } else {
        // ---- gather: masked neighbor sum -> A2 cols 512..767 ----
        int e = (bx - NB_WP - NB_GB - NB_CB - NB_CA) * 256 + t;  // MM*64
        int token = e >> 6;
        int lane = e & 63;
        int b = token >> 11;
        const int* ip = idx + token * NNB;
        const int* mp = mask + token * NNB;
        const float* hb = h + (size_t)b * SS * HH;
        float4 acc = make_float4(0.f, 0.f, 0.f, 0.f);
        #pragma unroll
        for (int n = 0; n < NNB; ++n) {
            int id = ip[n];
            int mk = mp[n];
            if (mk != 0 && id > 0) {
                const float4 v =
                    *(const float4*)(hb + (size_t)(id - 1) * HH + lane * 4);
                acc.x += v.x; acc.y += v.y; acc.z += v.z; acc.w += v.w;
            }
        }
        size_t o = (size_t)token * K2 + 512 + lane * 4;
        *(__half2*)(g_A2 + o)     = __floats2half2_rn(acc.x, acc.y);
        *(__half2*)(g_A2 + o + 2) = __floats2half2_rn(acc.z, acc.w);
    }
}

// ---------------------------------------------------------------- mma GEMM
// gates = A2 @ B2^T (perm cols) + gbias -> fused LSTM -> out.  K=768.
// 128x128 block, 8 warps (32m x 64n per warp), fp16 single-pass, fp32 accum.
// Double-chunk 3-deep cp.async pipeline, 48 KB static smem, LDSM addresses
// hoisted out of the k-loop (only the stage base varies).
#define CHUNK_B 8192               // one chunk: A 4K + B 4K
#define STG2_B 16384               // double-chunk stage

#define DECL4(p) float p##_0 = 0.f, p##_1 = 0.f, p##_2 = 0.f, p##_3 = 0.f

#define BJ_BLOCK(SB, OFFB, CA0, CA1, CB0, CB1)                                 \
    do {                                                                       \
        uint32_t bh0, bh1, bh2, bh3;                                           \
        LDSM_X4(bh0, bh1, bh2, bh3, (SB) + (OFFB));                            \
        MMA4(CA0, ah0_0, ah0_1, ah0_2, ah0_3, bh0, bh2);                       \
        MMA4(CA1, ah0_0, ah0_1, ah0_2, ah0_3, bh1, bh3);                       \
        MMA4(CB0, ah1_0, ah1_1, ah1_2, ah1_3, bh0, bh2);                       \
        MMA4(CB1, ah1_0, ah1_1, ah1_2, ah1_3, bh1, bh3);                       \
    } while (0)

#define COMPUTE_CHUNK(SBexpr)                                                  \
    do {                                                                       \
        const uint32_t SB = (SBexpr);                                          \
        uint32_t ah0_0, ah0_1, ah0_2, ah0_3, ah1_0, ah1_1, ah1_2, ah1_3;       \
        LDSM_X4(ah0_0, ah0_1, ah0_2, ah0_3, SB + offa);                        \
        LDSM_X4(ah1_0, ah1_1, ah1_2, ah1_3, SB + offc);                        \
        BJ_BLOCK(SB, offb0, C00, C01, C10, C11);                               \
        BJ_BLOCK(SB, offb1, C02, C03, C12, C13);                               \
        BJ_BLOCK(SB, offb2, C04, C05, C14, C15);                               \
        BJ_BLOCK(SB, offb3, C06, C07, C16, C17);                               \
    } while (0)

#define LSTM_E(i0, i1, f0, f1, o0, o1, u0, u1, MME, HCE, gI, gF, gO, gU)       \
    do {                                                                       \
        float2 cv = *(const float2*)(cin + (size_t)(MME) * HH + (HCE));        \
        float ivx = (i0) + gI.x, ivy = (i1) + gI.y;                            \
        float fvx = (f0) + gF.x, fvy = (f1) + gF.y;                            \
        float ovx = (o0) + gO.x, ovy = (o1) + gO.y;                            \
        float uvx = (u0) + gU.x, uvy = (u1) + gU.y;                            \
        float ncx = sigmoidf_(fvx) * cv.x + sigmoidf_(ivx) * tanhf(uvx);       \
        float ncy = sigmoidf_(fvy) * cv.y + sigmoidf_(ivy) * tanhf(uvy);       \
        float2 nh = make_float2(sigmoidf_(ovx) * tanhf(ncx),                   \
                                sigmoidf_(ovy) * tanhf(ncy));                  \
        *(float2*)(out + (size_t)(MME) * HH + (HCE)) = nh;                     \
        *(float2*)(out + (size_t)MM * HH + (size_t)(MME) * HH + (HCE)) =       \
            make_float2(ncx, ncy);                                             \
    } while (0)

__global__ __launch_bounds__(256, 2)
void mma_gemm(const float* __restrict__ cin, float* __restrict__ out) {
    constexpr int NS = K2 / 32;                  // 24 double-chunk stages

    const __half* __restrict__ A = g_A2;
    const __half* __restrict__ B = g_B2;

    __shared__ __align__(128) char smem_buf[3 * STG2_B];   // 48 KB static
    const uint32_t sb = smem_u32(smem_buf);
    const int tid = threadIdx.x;
    const int wid = tid >> 5, lid = tid & 31;
    const int wm = wid & 3, wn = wid >> 2;       // 4 x 2 warp grid
    const int bm = blockIdx.y * 128, bn = blockIdx.x * 128;

    // hoisted LDSM offsets (stage-base-relative; loop-invariant)
    const uint32_t KB = (uint32_t)(lid >> 4) * 16;
    const int la = lid & 15;
    const int rowa = wm * 32 + la;
    const uint32_t offa = rowa * 32 + (KB ^ ((rowa & 4) << 2));
    const uint32_t offc = (rowa + 16) * 32 + (KB ^ ((rowa & 4) << 2));
    const int rowb = wn * 64 + la;
    const uint32_t swb = (KB ^ ((rowb & 4) << 2));
    const uint32_t offb0 = 4096 + rowb * 32 + swb;
    const uint32_t offb1 = 4096 + (rowb + 16) * 32 + swb;
    const uint32_t offb2 = 4096 + (rowb + 32) * 32 + swb;
    const uint32_t offb3 = 4096 + (rowb + 48) * 32 + swb;

    DECL4(C00); DECL4(C01); DECL4(C02); DECL4(C03);
    DECL4(C04); DECL4(C05); DECL4(C06); DECL4(C07);
    DECL4(C10); DECL4(C11); DECL4(C12); DECL4(C13);
    DECL4(C14); DECL4(C15); DECL4(C16); DECL4(C17);

    // stage loader: 2 chunks per stage, one 16B cp.async per tile per chunk
    const int lrow = tid >> 1;                   // 0..127
    const uint32_t loff = (uint32_t)lrow * 32 +
                          (((uint32_t)(tid & 1) * 16) ^ ((lrow & 4) << 2));
    const int le8 = (tid & 1) * 8;               // 8 halves = 16 B

#define LOAD_STAGE2(st, s2)                                                    \
    {                                                                          \
        const int kA_ = (s2) * 32;                                             \
        const uint32_t b0_ = sb + (uint32_t)(st) * STG2_B + loff;              \
        const size_t gaA_ = (size_t)(bm + lrow) * K2 + kA_ + le8;              \
        const size_t gbA_ = (size_t)(bn + lrow) * K2 + kA_ + le8;              \
        cp_async16(b0_, A + gaA_);                                             \
        cp_async16(b0_ + 4096, B + gbA_);                                      \
        cp_async16(b0_ + CHUNK_B, A + gaA_ + 16);                              \
        cp_async16(b0_ + CHUNK_B + 4096, B + gbA_ + 16);                       \
    }

    LOAD_STAGE2(0, 0);
    cp_commit();
    LOAD_STAGE2(1, 1);
    cp_commit();

    int s_cur = 0;
    int s_nxt = 2;

    #pragma unroll 1
    for (int s2 = 0; s2 < NS; ++s2) {
        cp_wait<1>();
        __syncthreads();
        if (s2 + 2 < NS) LOAD_STAGE2(s_nxt, s2 + 2);
        cp_commit();

        const uint32_t SBase = sb + (uint32_t)s_cur * STG2_B;
        COMPUTE_CHUNK(SBase);
        COMPUTE_CHUNK(SBase + CHUNK_B);

        s_cur = (s_cur == 2) ? 0 : s_cur + 1;
        s_nxt = (s_nxt == 2) ? 0 : s_nxt + 1;
    }
#undef LOAD_STAGE2

    __syncthreads();

    // -------- fused LSTM epilogue (permuted N puts i/f/o/u in-thread) ------
    const int quad = lid >> 2, tq = lid & 3;
    const int bi = blockIdx.y >> 4;              // batch (16 m-tiles per batch)
    const float* gbp = g_gbias + bi * G4 + blockIdx.x * 128 + wn * 64 + tq * 2;
    float2 gI0 = *(const float2*)(gbp + 0);
    float2 gF0 = *(const float2*)(gbp + 8);
    float2 gO0 = *(const float2*)(gbp + 16);
    float2 gU0 = *(const float2*)(gbp + 24);
    float2 gI1 = *(const float2*)(gbp + 32);
    float2 gF1 = *(const float2*)(gbp + 40);
    float2 gO1 = *(const float2*)(gbp + 48);
    float2 gU1 = *(const float2*)(gbp + 56);
    const int m0 = bm + wm * 32 + quad;
    const int hc0 = blockIdx.x * 32 + wn * 16 + tq * 2;
    const int hc1 = hc0 + 8;
    // mi=0
    LSTM_E(C00_0, C00_1, C01_0, C01_1, C02_0, C02_1, C03_0, C03_1,
           m0, hc0, gI0, gF0, gO0, gU0);
    LSTM_E(C00_2, C00_3, C01_2, C01_3, C02_2, C02_3, C03_2, C03_3,
           m0 + 8, hc0, gI0, gF0, gO0, gU0);
    LSTM_E(C04_0, C04_1, C05_0, C05_1, C06_0, C06_1, C07_0, C07_1,
           m0, hc1, gI1, gF1, gO1, gU1);
    LSTM_E(C04_2, C04_3, C05_2, C05_3, C06_2, C06_3, C07_2, C07_3,
           m0 + 8, hc1, gI1, gF1, gO1, gU1);
    // mi=1
    LSTM_E(C10_0, C10_1, C11_0, C11_1, C12_0, C12_1, C13_0, C13_1,
           m0 + 16, hc0, gI0, gF0, gO0, gU0);
    LSTM_E(C10_2, C10_3, C11_2, C11_3, C12_2, C12_3, C13_2, C13_3,
           m0 + 24, hc0, gI0, gF0, gO0, gU0);
    LSTM_E(C14_0, C14_1, C15_0, C15_1, C16_0, C16_1, C17_0, C17_1,
           m0 + 16, hc1, gI1, gF1, gO1, gU1);
    LSTM_E(C14_2, C14_3, C15_2, C15_3, C16_2, C16_3, C17_2, C17_3,
           m0 + 24, hc1, gI1, gF1, gO1, gU1);
}

// ----------------------------------------------------------------------------
extern "C" void kernel_launch(void* const* d_in, const int* in_sizes, int n_in,
                              void* d_out, int out_size) {
    const float* x    = (const float*)d_in[0];
    const float* h    = (const float*)d_in[1];
    const float* c    = (const float*)d_in[2];
    const float* g    = (const float*)d_in[3];
    const int*   idx  = (const int*)d_in[4];
    const int*   mask = (const int*)d_in[5];
    // d_in[6] Wh_a, d_in[8..12]: unused — softmax over logits*1e-25 is exactly
    // uniform in fp32, so the attention score is 1/16 for every neighbor.
    const float* Wn_a = (const float*)d_in[7];
    const float* Wh   = (const float*)d_in[13];
    const float* Wn   = (const float*)d_in[14];
    const float* U    = (const float*)d_in[15];
    const float* V    = (const float*)d_in[16];
    const float* Vb   = (const float*)d_in[17];
    float* out = (float*)d_out;

    // 1. all prep in one launch (W' GEMM overlaps the memory-bound ranges)
    prep_all<<<NB_TOT, 256>>>(h, x, idx, mask, Wh, U, Wn, Wn_a, g, V, Vb);
    // 2. gates = [h|x|agg] @ [Wh;U;W'] + gbias, fused LSTM -> out
    mma_gemm<<<dim3(8, MM / 128), 256>>>(c, out);
}